// round 16
// baseline (speedup 1.0000x reference)
#include <cuda_runtime.h>
#include <math.h>

// Fixed shapes: x (4, 32, 8192, 64) fp32, token_positions = arange(8192)
#define SEQ        8192
#define LOG2_THETA 13.2877123795494489f // log2(10000), fp32
#define N8_TOTAL   (4 * 32 * SEQ * 8)   // 8,388,608 32B chunks
#define HALF8      (N8_TOTAL / 2)       // 4,194,304; div by 8 and by 8*8192
                                        //  -> chunk pairs share (p, j2)

// Merge of the two best mechanisms measured so far:
//  - LDG.256/STG.256 (R15: halves memory instruction count, R9-class DRAM%)
//  - staggered two-burst pipeline with SHARED trig (R9/R12: 2 sincosf per
//    32B, loads in flight during the store phase, <=8 lines/warp per burst).
// Plain cache policy everywhere (R8/R11: all hints lost).
__global__ void __launch_bounds__(256, 6)
rope_v8x2(const float* __restrict__ x, float* __restrict__ out,
          const int* __restrict__ pos) {
    int i  = blockIdx.x * 256 + threadIdx.x;    // chunk index, 0..HALF8-1
    int j2 = i & 7;                             // 8-float chunk within row
    int p  = (i >> 3) & (SEQ - 1);              // seq position

    const float* xa = x + ((size_t)i << 3);
    const float* xb = x + (((size_t)i + HALF8) << 3);
    float*       oa = out + ((size_t)i << 3);
    float*       ob = out + (((size_t)i + HALF8) << 3);

    // ---- Burst 1: 256-bit load of chunk A ----
    float a0, a1, a2, a3, a4, a5, a6, a7;
    asm volatile("ld.global.v8.b32 {%0,%1,%2,%3,%4,%5,%6,%7}, [%8];"
        : "=f"(a0), "=f"(a1), "=f"(a2), "=f"(a3),
          "=f"(a4), "=f"(a5), "=f"(a6), "=f"(a7) : "l"(xa));

    // ---- Trig under A's DRAM latency; shared by both chunks ----
    float posf = (float)__ldg(&pos[p]);
    int   k0   = j2 * 4;
    float c0, s0, c1, s1, c2, s2, c3, s3;
    sincosf(posf * exp2f(-(float)(k0 + 0) * (LOG2_THETA / 32.0f)), &s0, &c0);
    sincosf(posf * exp2f(-(float)(k0 + 1) * (LOG2_THETA / 32.0f)), &s1, &c1);
    sincosf(posf * exp2f(-(float)(k0 + 2) * (LOG2_THETA / 32.0f)), &s2, &c2);
    sincosf(posf * exp2f(-(float)(k0 + 3) * (LOG2_THETA / 32.0f)), &s3, &c3);

    // ---- Burst 2: 256-bit load of chunk B (in flight behind A's stores) ----
    float b0, b1, b2, b3, b4, b5, b6, b7;
    asm volatile("ld.global.v8.b32 {%0,%1,%2,%3,%4,%5,%6,%7}, [%8];"
        : "=f"(b0), "=f"(b1), "=f"(b2), "=f"(b3),
          "=f"(b4), "=f"(b5), "=f"(b6), "=f"(b7) : "l"(xb));

    // ---- Rotate + store A ----
    {
        float o0 = c0 * a0 - s0 * a1,  o1 = s0 * a0 + c0 * a1;
        float o2 = c1 * a2 - s1 * a3,  o3 = s1 * a2 + c1 * a3;
        float o4 = c2 * a4 - s2 * a5,  o5 = s2 * a4 + c2 * a5;
        float o6 = c3 * a6 - s3 * a7,  o7 = s3 * a6 + c3 * a7;
        asm volatile("st.global.v8.b32 [%0], {%1,%2,%3,%4,%5,%6,%7,%8};"
            :: "l"(oa), "f"(o0), "f"(o1), "f"(o2), "f"(o3),
               "f"(o4), "f"(o5), "f"(o6), "f"(o7) : "memory");
    }
    // ---- Rotate + store B ----
    {
        float o0 = c0 * b0 - s0 * b1,  o1 = s0 * b0 + c0 * b1;
        float o2 = c1 * b2 - s1 * b3,  o3 = s1 * b2 + c1 * b3;
        float o4 = c2 * b4 - s2 * b5,  o5 = s2 * b4 + c2 * b5;
        float o6 = c3 * b6 - s3 * b7,  o7 = s3 * b6 + c3 * b7;
        asm volatile("st.global.v8.b32 [%0], {%1,%2,%3,%4,%5,%6,%7,%8};"
            :: "l"(ob), "f"(o0), "f"(o1), "f"(o2), "f"(o3),
               "f"(o4), "f"(o5), "f"(o6), "f"(o7) : "memory");
    }
}

extern "C" void kernel_launch(void* const* d_in, const int* in_sizes, int n_in,
                              void* d_out, int out_size) {
    const float* x   = (const float*)d_in[0];
    const int*   pos = (const int*)d_in[1];
    float*       out = (float*)d_out;

    // 4,194,304 threads = 16384 blocks of 256
    rope_v8x2<<<HALF8 / 256, 256>>>(x, out, pos);
}

// round 17
// speedup vs baseline: 1.0130x; 1.0130x over previous
#include <cuda_runtime.h>
#include <math.h>

// Fixed shapes: x (4, 32, 8192, 64) fp32, token_positions = arange(8192)
#define SEQ       8192
#define NF4_ROW   16                    // 64 floats / 4 per row
#define SLICE_F4  (SEQ * NF4_ROW)       // 131072 float4 per (b,h) slice
#define N4_TOTAL  (128 * SLICE_F4)      // 16,777,216 float4 total
#define HALF_F4   (N4_TOTAL / 2)        // = 64 * SLICE_F4 -> streams share (p,j)
#define LOG2_THETA 13.2877123795494489f // log2(10000), fp32
#define RATIO      0.74989420933245580f // 10000^(-1/32): invf(k+1) = invf(k)*RATIO

// CONVERGED KERNEL (R9 + one free cleanup). Design decisions, all measured:
//  - ILP=2, both LDG.128 front-batched BEFORE the trig (R9: 82.6% DRAM;
//    ILP=4 front-batched/staggered, LDG.256, and v8x2 all 81-82% — worse).
//  - Streams i and i+HALF_F4 are an exact slice-multiple apart -> identical
//    (position, freq) -> ONE set of cos/sin serves both (no table, no smem,
//    no barrier, no block prologue — every table variant measured slower).
//  - Plain LDG/STG: .cs (R8), .cg (R11) both lost to default cache policy.
//  - 256-thread blocks (R14: 512 worse), flat grid (R13: persistent worse),
//    (256,6) reg budget (R6: tighter cap spills).
//  - fp32 exp2f/sincosf: rel_err 6.3e-5 vs 1e-3 budget (R6+).
__global__ void __launch_bounds__(256, 6)
rope_inline(const float4* __restrict__ x, float4* __restrict__ out,
            const int* __restrict__ pos) {
    int i = blockIdx.x * 256 + threadIdx.x;      // 0 .. HALF_F4-1
    int j = i & (NF4_ROW - 1);                   // float4 within row
    int p = (i >> 4) & (SEQ - 1);                // seq position

    // ---- Front-batch both loads: DRAM latency covers the trig below ----
    float4 v0 = x[i];
    float4 v1 = x[i + HALF_F4];

    // ---- Inline trig for pairs k = 2j, 2j+1 (shared by both streams) ----
    float posf  = (float)__ldg(&pos[p]);
    float invf0 = exp2f(-(float)(2 * j) * (LOG2_THETA / 32.0f));
    float invf1 = invf0 * RATIO;                 // replaces second exp2f
    float c0, s0, c1, s1;
    sincosf(posf * invf0, &s0, &c0);
    sincosf(posf * invf1, &s1, &c1);

    // ---- Rotate + store ----
    float4 o;
    o.x = c0 * v0.x - s0 * v0.y;  o.y = s0 * v0.x + c0 * v0.y;
    o.z = c1 * v0.z - s1 * v0.w;  o.w = s1 * v0.z + c1 * v0.w;
    out[i] = o;
    o.x = c0 * v1.x - s0 * v1.y;  o.y = s0 * v1.x + c0 * v1.y;
    o.z = c1 * v1.z - s1 * v1.w;  o.w = s1 * v1.z + c1 * v1.w;
    out[i + HALF_F4] = o;
}

extern "C" void kernel_launch(void* const* d_in, const int* in_sizes, int n_in,
                              void* d_out, int out_size) {
    const float4* x   = (const float4*)d_in[0];
    const int*    pos = (const int*)d_in[1];
    float4*       out = (float4*)d_out;

    // 8,388,608 threads = 32768 blocks of 256
    rope_inline<<<HALF_F4 / 256, 256>>>(x, out, pos);
}